// round 5
// baseline (speedup 1.0000x reference)
#include <cuda_runtime.h>
#include <math.h>

// Fixed dataset shape: B=8, L=512, V=16, K=8.
// out = concat(mask[B,L,V*K], gains[B,L]) as float32.

#define NT 128
#define MAXN 64
#define L_FIXED 512

__global__ __launch_bounds__(NT)
void gp_group_kernel(const float* __restrict__ t,
                     const int* __restrict__ vid,
                     const float* __restrict__ noise,
                     const float* __restrict__ outscale,
                     const float* __restrict__ lenscale,
                     const float* __restrict__ alpha,
                     float* __restrict__ outmask,
                     float* __restrict__ outgains,
                     int B, int L, int V, int K) {
    // Separate static shared objects -> provably no aliasing for ptxas.
    __shared__ float  C_[MAXN][MAXN + 1];
    __shared__ float  W_[MAXN][MAXN + 1];
    __shared__ float  colk[MAXN];
    __shared__ float  ts[MAXN];
    __shared__ float  tsu[MAXN];
    __shared__ float  invdiag[MAXN];
    __shared__ double sums[MAXN];
    __shared__ double warptot[4];
    __shared__ int    oidx[MAXN];
    __shared__ int    tmpidx[MAXN];
    __shared__ int    nsh;

    const int v = blockIdx.x;
    const int b = blockIdx.y;
    const int tid = threadIdx.x;
    const int lane = tid & 31;
    const int warp = tid >> 5;

    const float* trow = t + (size_t)b * L;
    const int* vrow = vid + (size_t)b * L;

    // ---- 1. order-preserving compaction (warp 0) ----
    if (warp == 0) {
        int cnt = 0;
        #pragma unroll 4
        for (int base = 0; base < L_FIXED; base += 32) {
            int i = base + lane;
            bool p = (vrow[i] == v);
            unsigned m = __ballot_sync(0xffffffffu, p);
            if (p) {
                int pos = cnt + __popc(m & ((1u << lane) - 1u));
                if (pos < MAXN) {
                    tmpidx[pos] = i;
                    tsu[pos] = trow[i];
                }
            }
            cnt += __popc(m);
        }
        if (lane == 0) nsh = (cnt < MAXN) ? cnt : MAXN;
    }
    __syncthreads();
    const int n = nsh;
    if (n == 0) return;

    // ---- 2. stable rank sort by time ----
    if (tid < n) {
        float tj = tsu[tid];
        int r = 0;
        #pragma unroll 4
        for (int k2 = 0; k2 < n; k2++) {
            float tk = tsu[k2];
            r += (tk < tj) || (tk == tj && k2 < tid);
        }
        ts[r] = tj;
        oidx[r] = tmpidx[tid];
    }
    __syncthreads();

    const float  os  = outscale[v];
    const float  nz  = noise[v];
    const float  lsv = lenscale[v];
    const float  al  = alpha[v];
    const float  inv2al2 = 1.0f / (2.0f * al * lsv * lsv);
    const double osd = (double)os;

    // ---- 3. fill Kn (C_) and Kxx (W_), upper triangle + mirror ----
    for (int idx = tid; idx < n * MAXN; idx += NT) {
        int i = idx >> 6;
        int j = idx & (MAXN - 1);
        if (j < n) {
            if (i < j) {
                float d = ts[i] - ts[j];
                float kij = os * expf(-al * log1pf(d * d * inv2al2));
                C_[i][j] = kij; C_[j][i] = kij;
                W_[i][j] = kij; W_[j][i] = kij;
            } else if (i == j) {
                C_[i][i] = os + nz + 1e-5f;
                W_[i][i] = os;
            }
        }
    }
    __syncthreads();

    // ---- 4. Cholesky (outer-product, unscaled) ----
    const int kB = (n > 32) ? (n - 32) : 0;
    // Phase A (only when n > 32): preload pivot column into colk.
    for (int k = 0; k < kB; k++) {
        for (int j = k + tid; j < n; j += NT) colk[j] = C_[j][k];
        __syncthreads();
        float invd = 1.0f / colk[k];
        int i = k + 1 + tid;
        if (i < n) {
            float cik = colk[i] * invd;
            #pragma unroll 4
            for (int j = k + 1; j <= i; j++)
                C_[i][j] -= cik * colk[j];
        }
        __syncthreads();
    }
    // Phase B: last <=32 steps, warp 0, fixed lane<->row, shuffle broadcasts.
    if (warp == 0) {
        const int row = kB + lane;
        const bool haverow = (row < n);
        for (int k = kB; k <= n - 2; k++) {
            float w = haverow ? C_[row][k] : 0.0f;   // own-row element
            float dkk = __shfl_sync(0xffffffffu, w, k - kB);
            float invd = 1.0f / dkk;
            float cik = w * invd;
            bool act = haverow && (row > k);
            for (int j = k + 1; j < n; j++) {
                float cj = __shfl_sync(0xffffffffu, w, j - kB);
                if (act && j <= row)
                    C_[row][j] -= cik * cj;
            }
        }
    }
    __syncthreads();
    // Scale: L[:,k] = rawcol_k / sqrt(d_k)
    for (int kk = tid; kk < n; kk += NT) {
        float s = sqrtf(C_[kk][kk]);
        float inv = 1.0f / s;
        invdiag[kk] = inv;
        for (int i = kk; i < n; i++) C_[i][kk] *= inv;
    }
    __syncthreads();

    // ---- 5. forward solve, thread-per-column, register-rotated recurrence,
    //         fused fp64 cum-of-squares. ----
    if (tid < n) {
        const int j = tid;
        double cum = 0.0;
        float u  = W_[0][j];
        float u1 = (n > 1) ? W_[1][j] : 0.0f;
        for (int i = 0; i < n; i++) {
            float wi = u * invdiag[i];
            cum += (double)wi * (double)wi;
            double var = osd - cum;
            W_[i][j] = (float)(var > 1e-12 ? var : 1e-12);
            float c1 = (i + 1 < n) ? C_[i + 1][i] : 0.0f;
            float c2 = (i + 2 < n) ? C_[i + 2][i] : 0.0f;
            float w2 = (i + 2 < n) ? W_[i + 2][j] : 0.0f;
            u  = u1 - c1 * wi;
            u1 = w2 - c2 * wi;
            #pragma unroll 4
            for (int r = i + 3; r < n; r++)
                W_[r][j] -= C_[r][i] * wi;
        }
    }
    __syncthreads();

    // ---- 6. row sums of posterior stds (4-way fp64 accumulators) ----
    for (int i = tid; i < n; i += NT) {
        double a0 = 0.0, a1 = 0.0, a2 = 0.0, a3 = 0.0;
        int j = 0;
        for (; j + 3 < n; j += 4) {
            a0 += (double)sqrtf(W_[i][j]);
            a1 += (double)sqrtf(W_[i][j + 1]);
            a2 += (double)sqrtf(W_[i][j + 2]);
            a3 += (double)sqrtf(W_[i][j + 3]);
        }
        for (; j < n; j++) a0 += (double)sqrtf(W_[i][j]);
        sums[i] = (a0 + a1) + (a2 + a3);
    }
    __syncthreads();

    // ---- 7. gains + block-wide fp64 inclusive scan (shuffles) ----
    double g = 0.0;
    if (tid < n) {
        double prevs = (tid == 0) ? sqrt(osd) * (double)n : sums[tid - 1];
        g = prevs - sums[tid];
        if (g < 0.0) g = 0.0;
    }
    double x = g;
    #pragma unroll
    for (int off = 1; off < 32; off <<= 1) {
        double y = __shfl_up_sync(0xffffffffu, x, off);
        if (lane >= off) x += y;
    }
    if (lane == 31) warptot[warp] = x;
    __syncthreads();
    double woff = 0.0;
    for (int w2 = 0; w2 < warp; w2++) woff += warptot[w2];
    x += woff;
    double totcg = (warptot[0] + warptot[1]) + (warptot[2] + warptot[3]);
    if (totcg < 1e-12) totcg = 1e-12;

    // ---- 8. group assignment + scatter ----
    if (tid < n) {
        double frac = (x - 0.5 * g) / totcg;
        int gbin = (int)floor(frac * (double)K);
        gbin = gbin < 0 ? 0 : (gbin > K - 1 ? K - 1 : gbin);
        int l = oidx[tid];
        size_t row = (size_t)(b * L + l);
        outmask[row * (size_t)(V * K) + (size_t)(v * K + gbin)] = 1.0f;
        outgains[row] = (float)g;
    }
}

__global__ void zero_kernel(float* __restrict__ p, int nElem) {
    int i = blockIdx.x * blockDim.x + threadIdx.x;
    if (i < nElem) p[i] = 0.0f;
}

extern "C" void kernel_launch(void* const* d_in, const int* in_sizes, int n_in,
                              void* d_out, int out_size) {
    const float* t       = (const float*)d_in[0];
    const int*   vid     = (const int*)d_in[2];
    const float* noise   = (const float*)d_in[3];
    const float* outsc   = (const float*)d_in[4];
    const float* lensc   = (const float*)d_in[5];
    const float* alph    = (const float*)d_in[6];

    int BL = in_sizes[0];            // B*L
    int V  = in_sizes[3];
    int L  = L_FIXED;
    int B  = BL / L;
    int VK1 = out_size / BL;         // V*K + 1
    int K  = (VK1 - 1) / V;

    float* outp  = (float*)d_out;
    float* gains = outp + (size_t)BL * (size_t)(VK1 - 1);

    zero_kernel<<<(out_size + 255) / 256, 256>>>(outp, out_size);

    dim3 grid(V, B);
    gp_group_kernel<<<grid, NT>>>(t, vid, noise, outsc, lensc, alph,
                                  outp, gains, B, L, V, K);
}

// round 6
// speedup vs baseline: 1.7998x; 1.7998x over previous
#include <cuda_runtime.h>
#include <math.h>

// Fixed dataset shape: B=8, L=512, V=16, K=8.
// out = concat(mask[B,L,V*K], gains[B,L]) as float32.

#define NT 128
#define MAXN 64
#define L_FIXED 512
#define NCHUNK (L_FIXED / 32)

__global__ __launch_bounds__(NT)
void gp_group_kernel(const float* __restrict__ t,
                     const int* __restrict__ vid,
                     const float* __restrict__ noise,
                     const float* __restrict__ outscale,
                     const float* __restrict__ lenscale,
                     const float* __restrict__ alpha,
                     float* __restrict__ outmask,
                     float* __restrict__ outgains,
                     int B, int L, int V, int K) {
    // Separate static shared objects -> provably no aliasing for ptxas.
    __shared__ float  C_[MAXN][MAXN + 1];
    __shared__ float  W_[MAXN][MAXN + 1];
    __shared__ float  ts[MAXN];
    __shared__ float  tsu[MAXN];
    __shared__ float  invdiag[MAXN];
    __shared__ double sums[MAXN];
    __shared__ double warptot[4];
    __shared__ int    oidx[MAXN];
    __shared__ int    tmpidx[MAXN];
    __shared__ int    nsh;

    const int v = blockIdx.x;
    const int b = blockIdx.y;
    const int tid = threadIdx.x;
    const int lane = tid & 31;
    const int warp = tid >> 5;

    const float* trow = t + (size_t)b * L_FIXED;
    const int* vrow = vid + (size_t)b * L_FIXED;

    // ---- 0. zero this CTA's mask columns: mask[b, 0..511, v*K .. v*K+7] ----
    {
        float4 z = make_float4(0.f, 0.f, 0.f, 0.f);
        float* base = outmask + ((size_t)b * L_FIXED) * (size_t)(V * K) + (size_t)(v * K);
        #pragma unroll
        for (int l = tid; l < L_FIXED; l += NT) {
            float4* p = (float4*)(base + (size_t)l * (V * K));
            p[0] = z; p[1] = z;                 // K=8 floats = 32 bytes
        }
    }

    // ---- 1. order-preserving compaction (warp 0), prefetched loads ----
    if (warp == 0) {
        int   myv[NCHUNK];
        float myt[NCHUNK];
        #pragma unroll
        for (int c = 0; c < NCHUNK; c++) {
            int i = c * 32 + lane;
            myv[c] = vrow[i];
            myt[c] = trow[i];
        }
        int cnt = 0;
        #pragma unroll
        for (int c = 0; c < NCHUNK; c++) {
            bool p = (myv[c] == v);
            unsigned m = __ballot_sync(0xffffffffu, p);
            if (p) {
                int pos = cnt + __popc(m & ((1u << lane) - 1u));
                if (pos < MAXN) {
                    tmpidx[pos] = c * 32 + lane;
                    tsu[pos] = myt[c];
                }
            }
            cnt += __popc(m);
        }
        if (lane == 0) nsh = (cnt < MAXN) ? cnt : MAXN;
    }
    __syncthreads();
    const int n = nsh;
    if (n == 0) return;     // mask columns already zeroed

    // ---- 2. stable rank sort by time ----
    if (tid < n) {
        float tj = tsu[tid];
        int r = 0;
        #pragma unroll 4
        for (int k2 = 0; k2 < n; k2++) {
            float tk = tsu[k2];
            r += (tk < tj) || (tk == tj && k2 < tid);
        }
        ts[r] = tj;
        oidx[r] = tmpidx[tid];
    }
    __syncthreads();

    const float  os  = outscale[v];
    const float  nz  = noise[v];
    const float  lsv = lenscale[v];
    const float  al  = alpha[v];
    const float  inv2al2 = 1.0f / (2.0f * al * lsv * lsv);
    const double osd = (double)os;

    // ---- 3. fill Kn (C_) and Kxx (W_), upper triangle + mirror ----
    for (int idx = tid; idx < n * MAXN; idx += NT) {
        int i = idx >> 6;
        int j = idx & (MAXN - 1);
        if (j < n) {
            if (i < j) {
                float d = ts[i] - ts[j];
                float kij = os * __expf(-al * __logf(1.0f + d * d * inv2al2));
                C_[i][j] = kij; C_[j][i] = kij;
                W_[i][j] = kij; W_[j][i] = kij;
            } else if (i == j) {
                C_[i][i] = os + nz + 1e-5f;
                W_[i][i] = os;
            }
        }
    }
    __syncthreads();

    // ---- 4. Cholesky (outer-product, unscaled) ----
    // Phase A: >32 active rows -> all threads + __syncthreads.
    int k = 0;
    for (; k < n - 1 && (n - 1 - k) > 32; k++) {
        float invd = 1.0f / C_[k][k];
        int i = k + 1 + tid;
        if (i < n) {
            float cik = C_[i][k] * invd;
            #pragma unroll 4
            for (int j = k + 1; j <= i; j++)
                C_[i][j] -= cik * C_[j][k];
        }
        __syncthreads();
    }
    // Phase B: <=32 active rows -> warp 0 only, __syncwarp.
    if (warp == 0) {
        for (; k < n - 1; k++) {
            float invd = 1.0f / C_[k][k];
            int i = k + 1 + lane;
            if (i < n) {
                float cik = C_[i][k] * invd;
                #pragma unroll 4
                for (int j = k + 1; j <= i; j++)
                    C_[i][j] -= cik * C_[j][k];
            }
            __syncwarp();
        }
    }
    __syncthreads();
    // Scale: L[:,k] = rawcol_k / sqrt(d_k)
    for (int kk = tid; kk < n; kk += NT) {
        float s = sqrtf(C_[kk][kk]);
        float inv = 1.0f / s;
        invdiag[kk] = inv;
        for (int i = kk; i < n; i++) C_[i][kk] *= inv;
    }
    __syncthreads();

    // ---- 5. forward solve, thread-per-column, wnext carried in register,
    //         fused fp64 cum-of-squares ----
    if (tid < n) {
        const int j = tid;
        double cum = 0.0;
        float wnext = W_[0][j];
        for (int i = 0; i < n; i++) {
            float wi = wnext * invdiag[i];
            cum += (double)wi * (double)wi;
            double var = osd - cum;
            W_[i][j] = (float)(var > 1e-12 ? var : 1e-12);
            #pragma unroll 4
            for (int r = i + 1; r < n; r++) {
                float val = W_[r][j] - C_[r][i] * wi;
                W_[r][j] = val;
                if (r == i + 1) wnext = val;
            }
        }
    }
    __syncthreads();

    // ---- 6. row sums of posterior stds (4-way fp64 accumulators) ----
    for (int i = tid; i < n; i += NT) {
        double a0 = 0.0, a1 = 0.0, a2 = 0.0, a3 = 0.0;
        int j = 0;
        for (; j + 3 < n; j += 4) {
            a0 += (double)sqrtf(W_[i][j]);
            a1 += (double)sqrtf(W_[i][j + 1]);
            a2 += (double)sqrtf(W_[i][j + 2]);
            a3 += (double)sqrtf(W_[i][j + 3]);
        }
        for (; j < n; j++) a0 += (double)sqrtf(W_[i][j]);
        sums[i] = (a0 + a1) + (a2 + a3);
    }
    __syncthreads();

    // ---- 7. gains + block-wide fp64 inclusive scan (shuffles) ----
    double g = 0.0;
    if (tid < n) {
        double prevs = (tid == 0) ? sqrt(osd) * (double)n : sums[tid - 1];
        g = prevs - sums[tid];
        if (g < 0.0) g = 0.0;
    }
    double x = g;
    #pragma unroll
    for (int off = 1; off < 32; off <<= 1) {
        double y = __shfl_up_sync(0xffffffffu, x, off);
        if (lane >= off) x += y;
    }
    if (lane == 31) warptot[warp] = x;
    __syncthreads();
    double woff = 0.0;
    for (int w2 = 0; w2 < warp; w2++) woff += warptot[w2];
    x += woff;
    double totcg = (warptot[0] + warptot[1]) + (warptot[2] + warptot[3]);
    if (totcg < 1e-12) totcg = 1e-12;

    // ---- 8. group assignment + scatter ----
    if (tid < n) {
        double frac = (x - 0.5 * g) / totcg;
        int gbin = (int)floor(frac * (double)K);
        gbin = gbin < 0 ? 0 : (gbin > K - 1 ? K - 1 : gbin);
        int l = oidx[tid];
        size_t row = (size_t)(b * L_FIXED + l);
        outmask[row * (size_t)(V * K) + (size_t)(v * K + gbin)] = 1.0f;
        outgains[row] = (float)g;
    }
}

extern "C" void kernel_launch(void* const* d_in, const int* in_sizes, int n_in,
                              void* d_out, int out_size) {
    const float* t       = (const float*)d_in[0];
    const int*   vid     = (const int*)d_in[2];
    const float* noise   = (const float*)d_in[3];
    const float* outsc   = (const float*)d_in[4];
    const float* lensc   = (const float*)d_in[5];
    const float* alph    = (const float*)d_in[6];

    int BL = in_sizes[0];            // B*L
    int V  = in_sizes[3];
    int L  = L_FIXED;
    int B  = BL / L;
    int VK1 = out_size / BL;         // V*K + 1
    int K  = (VK1 - 1) / V;

    float* outp  = (float*)d_out;
    float* gains = outp + (size_t)BL * (size_t)(VK1 - 1);

    dim3 grid(V, B);
    gp_group_kernel<<<grid, NT>>>(t, vid, noise, outsc, lensc, alph,
                                  outp, gains, B, L, V, K);
}

// round 7
// speedup vs baseline: 2.2946x; 1.2749x over previous
#include <cuda_runtime.h>
#include <math.h>

// Fixed dataset shape: B=8, L=512, V=16, K=8.
// out = concat(mask[B,L,V*K], gains[B,L]) as float32.

#define NT 128
#define MAXN 64
#define L_FIXED 512
#define NCHUNK (L_FIXED / 32)
#define CSTRIDE (MAXN + 1)

// Forward-solve a 32-row triangular block for one RHS column j, register-
// resident, fully unrolled. Relies on zero padding: invd[i]=0 and C rows/cols
// zero outside the active n -> pad iterations are exact no-ops on cum.
// Writes v-values (scaled solve) to Vb[.][j] and posterior stds to W[off+.][j].
__device__ __noinline__ double solve32_block(
    const float (*__restrict__ C)[CSTRIDE],
    float (*__restrict__ W)[CSTRIDE],
    float (*__restrict__ Vb)[CSTRIDE],
    const float* __restrict__ invd,
    int off, int j, double cum, double osd)
{
    float w[32], wsq[32];
#pragma unroll
    for (int r = 0; r < 32; r++) w[r] = W[off + r][j];
#pragma unroll
    for (int i = 0; i < 32; i++) {
        float wi = w[i] * invd[off + i];
        wsq[i] = wi * wi;
        Vb[i][j] = wi;
#pragma unroll
        for (int r = i + 1; r < 32; r++)
            w[r] -= C[off + r][off + i] * wi;
    }
    // pairwise fp64 prefix: one chained DADD per 2 elements; stds off-chain
#pragma unroll
    for (int i = 0; i < 32; i += 2) {
        double a = (double)wsq[i];
        double pair = a + (double)wsq[i + 1];
        double ce = cum + a;
        double co = cum + pair;
        W[off + i][j]     = sqrtf(fmaxf((float)(osd - ce), 1e-12f));
        W[off + i + 1][j] = sqrtf(fmaxf((float)(osd - co), 1e-12f));
        cum = co;
    }
    return cum;
}

__global__ __launch_bounds__(NT)
void gp_group_kernel(const float* __restrict__ t,
                     const int* __restrict__ vid,
                     const float* __restrict__ noise,
                     const float* __restrict__ outscale,
                     const float* __restrict__ lenscale,
                     const float* __restrict__ alpha,
                     float* __restrict__ outmask,
                     float* __restrict__ outgains,
                     int B, int L, int V, int K) {
    __shared__ float  C_[MAXN][CSTRIDE];
    __shared__ float  W_[MAXN][CSTRIDE];
    __shared__ float  Vb[32][CSTRIDE];
    __shared__ float  ts[MAXN];
    __shared__ float  tsu[MAXN];
    __shared__ float  invdiag[MAXN];
    __shared__ double sums[MAXN];
    __shared__ double warptot[4];
    __shared__ int    oidx[MAXN];
    __shared__ int    tmpidx[MAXN];
    __shared__ int    nsh;

    const int v = blockIdx.x;
    const int b = blockIdx.y;
    const int tid = threadIdx.x;
    const int lane = tid & 31;
    const int warp = tid >> 5;

    const float* trow = t + (size_t)b * L_FIXED;
    const int* vrow = vid + (size_t)b * L_FIXED;

    // ---- 0. zero this CTA's mask columns: mask[b, :, v*K .. v*K+7] ----
    {
        float4 z = make_float4(0.f, 0.f, 0.f, 0.f);
        float* base = outmask + ((size_t)b * L_FIXED) * (size_t)(V * K) + (size_t)(v * K);
        #pragma unroll
        for (int l = tid; l < L_FIXED; l += NT) {
            float4* p = (float4*)(base + (size_t)l * (V * K));
            p[0] = z; p[1] = z;
        }
    }

    // ---- 1. order-preserving compaction (warp 0), prefetched loads ----
    if (warp == 0) {
        int   myv[NCHUNK];
        float myt[NCHUNK];
        #pragma unroll
        for (int c = 0; c < NCHUNK; c++) {
            int i = c * 32 + lane;
            myv[c] = vrow[i];
            myt[c] = trow[i];
        }
        int cnt = 0;
        #pragma unroll
        for (int c = 0; c < NCHUNK; c++) {
            bool p = (myv[c] == v);
            unsigned m = __ballot_sync(0xffffffffu, p);
            if (p) {
                int pos = cnt + __popc(m & ((1u << lane) - 1u));
                if (pos < MAXN) {
                    tmpidx[pos] = c * 32 + lane;
                    tsu[pos] = myt[c];
                }
            }
            cnt += __popc(m);
        }
        if (lane == 0) nsh = (cnt < MAXN) ? cnt : MAXN;
    }
    __syncthreads();
    const int n = nsh;
    if (n == 0) return;

    // ---- 2. stable rank sort by time ----
    if (tid < n) {
        float tj = tsu[tid];
        int r = 0;
        #pragma unroll 4
        for (int k2 = 0; k2 < n; k2++) {
            float tk = tsu[k2];
            r += (tk < tj) || (tk == tj && k2 < tid);
        }
        ts[r] = tj;
        oidx[r] = tmpidx[tid];
    }
    __syncthreads();

    const float  os  = outscale[v];
    const float  nz  = noise[v];
    const float  lsv = lenscale[v];
    const float  al  = alpha[v];
    const float  inv2al2 = 1.0f / (2.0f * al * lsv * lsv);
    const double osd = (double)os;

    // ---- 3. fill Kn (C_) and Kxx (W_) over the FULL 64x64, zero padding ----
    for (int idx = tid; idx < MAXN * MAXN; idx += NT) {
        int i = idx >> 6;
        int j = idx & (MAXN - 1);
        if (i < n && j < n) {
            if (i < j) {
                float d = ts[i] - ts[j];
                float kij = os * __expf(-al * __logf(1.0f + d * d * inv2al2));
                C_[i][j] = kij; C_[j][i] = kij;
                W_[i][j] = kij; W_[j][i] = kij;
            } else if (i == j) {
                C_[i][i] = os + nz + 1e-5f;
                W_[i][i] = os;
            }
        } else {
            C_[i][j] = 0.0f;
            W_[i][j] = 0.0f;
        }
    }
    __syncthreads();

    // ---- 4. Cholesky (outer-product, unscaled) ----
    // Phase A: >32 active rows -> warps 0-1 (64 threads), named barrier.
    if (warp < 2) {
        int t64 = tid;           // 0..63
        for (int k = 0; k < n - 1 && (n - 1 - k) > 32; k++) {
            float invd = __fdividef(1.0f, C_[k][k]);
            int i = k + 1 + t64;
            if (i < n) {
                float cik = C_[i][k] * invd;
                #pragma unroll 4
                for (int j = k + 1; j <= i; j++)
                    C_[i][j] -= cik * C_[j][k];
            }
            asm volatile("bar.sync 1, 64;" ::: "memory");
        }
    }
    // Phase B: last <=32 steps -> warp 0 only, __syncwarp.
    if (warp == 0) {
        for (int k = (n > 33 ? n - 33 : 0); k < n - 1; k++) {
            float invd = __fdividef(1.0f, C_[k][k]);
            int i = k + 1 + lane;
            if (i < n) {
                float cik = C_[i][k] * invd;
                #pragma unroll 4
                for (int j = k + 1; j <= i; j++)
                    C_[i][j] -= cik * C_[j][k];
            }
            __syncwarp();
        }
    }
    __syncthreads();
    // Scale: L[:,k] = rawcol_k * rsqrt(d_k); invdiag zero-padded above n.
    for (int kk = tid; kk < MAXN; kk += NT) {
        if (kk < n) {
            float inv = rsqrtf(C_[kk][kk]);
            invdiag[kk] = inv;
            for (int i = kk; i < n; i++) C_[i][kk] *= inv;
        } else {
            invdiag[kk] = 0.0f;
        }
    }
    __syncthreads();

    // ---- 5. forward solve, thread-per-column, register-blocked 32x32 ----
    if (tid < n) {
        const int j = tid;
        double cum = solve32_block(C_, W_, Vb, invdiag, 0, j, 0.0, osd);
        if (n > 32) {
            // coupling: residual k2 -= L21 @ v1  (v1 staged in Vb)
            float w2[32];
            #pragma unroll
            for (int r = 0; r < 32; r++) w2[r] = W_[32 + r][j];
            for (int i = 0; i < 32; i++) {
                float vi = Vb[i][j];
                #pragma unroll
                for (int r = 0; r < 32; r++)
                    w2[r] -= C_[32 + r][i] * vi;
            }
            #pragma unroll
            for (int r = 0; r < 32; r++) W_[32 + r][j] = w2[r];
            cum = solve32_block(C_, W_, Vb, invdiag, 32, j, cum, osd);
        }
    }
    __syncthreads();

    // ---- 6. row sums of posterior stds (W_ already holds stds) ----
    for (int i = tid; i < n; i += NT) {
        double a0 = 0.0, a1 = 0.0, a2 = 0.0, a3 = 0.0;
        int j = 0;
        for (; j + 3 < n; j += 4) {
            a0 += (double)W_[i][j];
            a1 += (double)W_[i][j + 1];
            a2 += (double)W_[i][j + 2];
            a3 += (double)W_[i][j + 3];
        }
        for (; j < n; j++) a0 += (double)W_[i][j];
        sums[i] = (a0 + a1) + (a2 + a3);
    }
    __syncthreads();

    // ---- 7. gains + block-wide fp64 inclusive scan (shuffles) ----
    double g = 0.0;
    if (tid < n) {
        double prevs = (tid == 0) ? sqrt(osd) * (double)n : sums[tid - 1];
        g = prevs - sums[tid];
        if (g < 0.0) g = 0.0;
    }
    double x = g;
    #pragma unroll
    for (int off = 1; off < 32; off <<= 1) {
        double y = __shfl_up_sync(0xffffffffu, x, off);
        if (lane >= off) x += y;
    }
    if (lane == 31) warptot[warp] = x;
    __syncthreads();
    double woff = 0.0;
    for (int w2i = 0; w2i < warp; w2i++) woff += warptot[w2i];
    x += woff;
    double totcg = (warptot[0] + warptot[1]) + (warptot[2] + warptot[3]);
    if (totcg < 1e-12) totcg = 1e-12;

    // ---- 8. group assignment + scatter ----
    if (tid < n) {
        double frac = (x - 0.5 * g) / totcg;
        int gbin = (int)floor(frac * (double)K);
        gbin = gbin < 0 ? 0 : (gbin > K - 1 ? K - 1 : gbin);
        int l = oidx[tid];
        size_t row = (size_t)(b * L_FIXED + l);
        outmask[row * (size_t)(V * K) + (size_t)(v * K + gbin)] = 1.0f;
        outgains[row] = (float)g;
    }
}

extern "C" void kernel_launch(void* const* d_in, const int* in_sizes, int n_in,
                              void* d_out, int out_size) {
    const float* t       = (const float*)d_in[0];
    const int*   vid     = (const int*)d_in[2];
    const float* noise   = (const float*)d_in[3];
    const float* outsc   = (const float*)d_in[4];
    const float* lensc   = (const float*)d_in[5];
    const float* alph    = (const float*)d_in[6];

    int BL = in_sizes[0];            // B*L
    int V  = in_sizes[3];
    int L  = L_FIXED;
    int B  = BL / L;
    int VK1 = out_size / BL;         // V*K + 1
    int K  = (VK1 - 1) / V;

    float* outp  = (float*)d_out;
    float* gains = outp + (size_t)BL * (size_t)(VK1 - 1);

    dim3 grid(V, B);
    gp_group_kernel<<<grid, NT>>>(t, vid, noise, outsc, lensc, alph,
                                  outp, gains, B, L, V, K);
}